// round 14
// baseline (speedup 1.0000x reference)
#include <cuda_runtime.h>
#include <math.h>

// Dims per reference: B=2, C=2, D=64, H=128, W=128
#define DD 64
#define HH 128
#define WW 128
#define VOLSZ (DD*HH*WW)       // 2^20
#define NTOT  (2*VOLSZ)        // 2^21
#define HWS   (HH*WW)
#define G_INIT ((NTOT/4)/256)  // 2048
#define GS4    ((NTOT/4)/256)  // 2048

#define EB  768
#define DB  768
#define MB  1024
#define DIRB 2048

// ---------------- scratch ----------------
__device__ float g_SRC[3*NTOT];
__device__ float g_SK [3*NTOT];
__device__ float g_B0 [3*NTOT];
__device__ float g_B1 [3*NTOT];
__device__ float g_B2 [3*NTOT];
__device__ float g_MA [2*NTOT];
__device__ float g_MB [2*NTOT];
__device__ float g_ACC[2*NTOT];

__device__ double g_sums[14];
__device__ int g_maxT[2], g_minT[2], g_maxP[2], g_minP[2];
__device__ int g_nzS[3][16];
__device__ int g_nzM[17];

enum { S_TP=0, S_FP, S_FN, S_CE, S_CONN, S_DIR,
       S_CL1, S_CL2, S_CL3, S_CL4, S_I1, S_U1, S_I2, S_U2 };

// ---------------- helpers ----------------
__device__ __forceinline__ float4 ld4(const float* p){ return *reinterpret_cast<const float4*>(p); }
__device__ __forceinline__ void   st4(float* p, float4 v){ *reinterpret_cast<float4*>(p) = v; }
__device__ __forceinline__ float4 f4min(float4 a, float4 b){
  return make_float4(fminf(a.x,b.x), fminf(a.y,b.y), fminf(a.z,b.z), fminf(a.w,b.w));
}
__device__ __forceinline__ float4 f4max(float4 a, float4 b){
  return make_float4(fmaxf(a.x,b.x), fmaxf(a.y,b.y), fmaxf(a.z,b.z), fmaxf(a.w,b.w));
}
template<bool MX> __device__ __forceinline__ float opf(float a, float b){
  return MX ? fmaxf(a,b) : fminf(a,b);
}
template<bool MX> __device__ __forceinline__ float4 opf4(float4 a, float4 b){
  return MX ? f4max(a,b) : f4min(a,b);
}
__device__ __forceinline__ float4 selpad(float4 v, bool ok, float pad){
  return ok ? v : make_float4(pad,pad,pad,pad);
}
__device__ __forceinline__ float h4max(float4 v){
  return fmaxf(fmaxf(v.x,v.y), fmaxf(v.z,v.w));
}

template<bool MX>
__device__ __forceinline__ float4 rw3bf(const float* rp, bool okl, bool okr, bool rowok){
  const float pad = MX ? -1e30f : 1e30f;
  float  l = rp[okl ? -1 : 0];
  float  r = rp[okr ?  4 : 3];
  float4 v = ld4(rp);
  l = okl ? l : pad;
  r = okr ? r : pad;
  float4 o;
  o.x = opf<MX>(opf<MX>(l,  v.x), v.y);
  o.y = opf<MX>(opf<MX>(v.x,v.y), v.z);
  o.z = opf<MX>(opf<MX>(v.y,v.z), v.w);
  o.w = opf<MX>(opf<MX>(v.z,v.w), r);
  return selpad(o, rowok, pad);
}

// 3x3x3 box pool over 4x4 tile at depth d (branch-free)
template<bool MX>
__device__ __forceinline__ void box27_4bf(const float* vbase, int d, int h0, int w0,
                                          float4 out[4]){
  const float pad = MX ? -1e30f : 1e30f;
  const float4 P4 = make_float4(pad,pad,pad,pad);
  out[0]=out[1]=out[2]=out[3]=P4;
  bool okl = (w0 > 0), okr = (w0 + 4 < WW);
  #pragma unroll
  for (int pz=0; pz<3; ++pz){
    int dd = d - 1 + pz;
    bool zok = (unsigned)dd < DD;
    const float* pp = vbase + (zok ? dd : (dd < 0 ? 0 : DD-1))*HWS;
    float4 rw[6];
    #pragma unroll
    for (int jr=0; jr<6; ++jr){
      int hh = h0 - 1 + jr;
      bool ok = zok & ((unsigned)hh < HH);
      const float* rp = pp + (((unsigned)hh < HH) ? hh : (hh < 0 ? 0 : HH-1))*WW + w0;
      rw[jr] = rw3bf<MX>(rp, okl, okr, ok);
    }
    #pragma unroll
    for (int j=0;j<4;j++)
      out[j] = opf4<MX>(out[j], opf4<MX>(rw[j], opf4<MX>(rw[j+1], rw[j+2])));
  }
}

// ---------------- reductions ----------------
__device__ __forceinline__ float warp_sum(float v){
  #pragma unroll
  for (int o=16; o; o>>=1) v += __shfl_down_sync(0xffffffffu, v, o);
  return v;
}
__device__ __forceinline__ void block_add(double* dst, float v){
  __shared__ float sh[8];
  v = warp_sum(v);
  if ((threadIdx.x & 31) == 0) sh[threadIdx.x >> 5] = v;
  __syncthreads();
  if (threadIdx.x == 0){
    float t = sh[0]+sh[1]+sh[2]+sh[3]+sh[4]+sh[5]+sh[6]+sh[7];
    atomicAdd(dst, (double)t);
  }
  __syncthreads();
}
__device__ __forceinline__ void block_maxf(int* dst, float v){
  __shared__ float sh[8];
  #pragma unroll
  for (int o=16; o; o>>=1) v = fmaxf(v, __shfl_down_sync(0xffffffffu, v, o));
  if ((threadIdx.x & 31) == 0) sh[threadIdx.x >> 5] = v;
  __syncthreads();
  if (threadIdx.x == 0){
    float m = sh[0];
    #pragma unroll
    for (int k=1;k<8;k++) m = fmaxf(m, sh[k]);
    atomicMax(dst, __float_as_int(m));
  }
  __syncthreads();
}
__device__ __forceinline__ void block_minf(int* dst, float v){
  __shared__ float sh[8];
  #pragma unroll
  for (int o=16; o; o>>=1) v = fminf(v, __shfl_down_sync(0xffffffffu, v, o));
  if ((threadIdx.x & 31) == 0) sh[threadIdx.x >> 5] = v;
  __syncthreads();
  if (threadIdx.x == 0){
    float m = sh[0];
    #pragma unroll
    for (int k=1;k<8;k++) m = fminf(m, sh[k]);
    atomicMin(dst, __float_as_int(m));
  }
  __syncthreads();
}

// ---------------- bodies ----------------
// soft_erode (7-pt cross), 4w x 4h x 2d tile (int offsets throughout)
__device__ __forceinline__ void erode_body(const float* __restrict__ src,
                                           float* __restrict__ dst, int tt, int et){
  int vb = tt >> 15;
  int f  = vb >> 1;
  if (g_nzS[f][et] == 0) return;
  int w0 = (tt & 31) << 2;
  int h0 = ((tt >> 5) & 31) << 2;
  int d0 = ((tt >> 10) & 31) << 1;
  const float* vbase = src + vb*VOLSZ;
  const float INF = 1e30f;

  float4 C[4][4];
  #pragma unroll
  for (int pz=0; pz<4; ++pz){
    int dd = d0 - 1 + pz;
    bool zok = (unsigned)dd < DD;
    const float* pp = vbase + (zok ? dd : (dd < 0 ? 0 : DD-1))*HWS + h0*WW + w0;
    #pragma unroll
    for (int j=0;j<4;j++)
      C[pz][j] = selpad(ld4(pp + j*WW), zok, INF);
  }
  float4 HB[2][2];
  bool okm = (h0 > 0), okp = (h0 + 4 < HH);
  #pragma unroll
  for (int s=0;s<2;s++){
    const float* pp = vbase + (d0+s)*HWS;
    HB[s][0] = selpad(ld4(pp + (okm ? h0-1 : 0)*WW + w0), okm, INF);
    HB[s][1] = selpad(ld4(pp + (okp ? h0+4 : HH-1)*WW + w0), okp, INF);
  }
  float L[2][4], R[2][4];
  bool okl = (w0 > 0), okr = (w0 + 4 < WW);
  #pragma unroll
  for (int s=0;s<2;s++){
    const float* pp = vbase + (d0+s)*HWS + h0*WW + w0;
    #pragma unroll
    for (int j=0;j<4;j++){
      float l = pp[j*WW + (okl ? -1 : 0)];
      float r = pp[j*WW + (okr ?  4 : 3)];
      L[s][j] = okl ? l : INF;
      R[s][j] = okr ? r : INF;
    }
  }
  float* obase = dst + vb*VOLSZ + d0*HWS + h0*WW + w0;
  float anymax = 0.f;
  #pragma unroll
  for (int s=0;s<2;s++){
    #pragma unroll
    for (int j=0;j<4;j++){
      float4 v = C[s+1][j];
      float4 w3;
      w3.x = fminf(fminf(L[s][j], v.x), v.y);
      w3.y = fminf(fminf(v.x, v.y), v.z);
      w3.z = fminf(fminf(v.y, v.z), v.w);
      w3.w = fminf(fminf(v.z, v.w), R[s][j]);
      float4 up = (j==0) ? HB[s][0] : C[s+1][j-1];
      float4 dn = (j==3) ? HB[s][1] : C[s+1][j+1];
      float4 m = f4min(w3, f4min(up, dn));
      m = f4min(m, f4min(C[s][j], C[s+2][j]));
      anymax = fmaxf(anymax, h4max(m));
      st4(obase + s*HWS + j*WW, m);
    }
  }
  if (anymax > 0.f) g_nzS[f][et+1] = 1;
}

// dilate27(er) + skel update, 4w x 4h x 2d tile, TWO-PASS over d-slices
// (smaller register live-set; overlap planes re-read from L1/L2).
__device__ __forceinline__ void dilate2_body(const float* __restrict__ img,
                                             const float* __restrict__ er,
                                             float* __restrict__ skel,
                                             int init, int tt, int dt){
  int vb = tt >> 15;
  int f  = vb >> 1;
  if (g_nzS[f][dt] == 0) return;
  int w0 = (tt & 31) << 2;
  int h0 = ((tt >> 5) & 31) << 2;
  int d0 = ((tt >> 10) & 31) << 1;
  const float* ebase = er + vb*VOLSZ;
  bool okl = (w0 > 0), okr = (w0 + 4 < WW);
  bool er_nz = (g_nzS[f][dt+1] != 0);
  int off = vb*VOLSZ + d0*HWS + h0*WW + w0;

  #pragma unroll
  for (int s=0;s<2;s++){
    float4 o4[4];
    if (er_nz){
      const float4 N4 = make_float4(-1e30f,-1e30f,-1e30f,-1e30f);
      o4[0]=o4[1]=o4[2]=o4[3]=N4;
      #pragma unroll
      for (int pz=0; pz<3; ++pz){
        int dd = d0 + s - 1 + pz;
        bool zok = (unsigned)dd < DD;
        const float* pp = ebase + (zok ? dd : (dd < 0 ? 0 : DD-1))*HWS;
        float4 rw[6];
        #pragma unroll
        for (int jr=0; jr<6; ++jr){
          int hh = h0 - 1 + jr;
          bool ok = zok & ((unsigned)hh < HH);
          const float* rp = pp + (((unsigned)hh < HH) ? hh : (hh < 0 ? 0 : HH-1))*WW + w0;
          rw[jr] = rw3bf<true>(rp, okl, okr, ok);
        }
        #pragma unroll
        for (int j=0;j<4;j++)
          o4[j] = f4max(o4[j], f4max(rw[j], f4max(rw[j+1], rw[j+2])));
      }
    } else {
      o4[0]=o4[1]=o4[2]=o4[3]=make_float4(0.f,0.f,0.f,0.f);
    }
    #pragma unroll
    for (int j=0;j<4;j++){
      float4 im = ld4(img + off + s*HWS + j*WW);
      float4 dl = make_float4(fmaxf(im.x-o4[j].x,0.f), fmaxf(im.y-o4[j].y,0.f),
                              fmaxf(im.z-o4[j].z,0.f), fmaxf(im.w-o4[j].w,0.f));
      if (init){
        st4(skel + off + s*HWS + j*WW, dl);
      } else {
        float4 sv = ld4(skel + off + s*HWS + j*WW);
        sv.x += fmaxf(dl.x - sv.x*dl.x, 0.f);
        sv.y += fmaxf(dl.y - sv.y*dl.y, 0.f);
        sv.z += fmaxf(dl.z - sv.z*dl.z, 0.f);
        sv.w += fmaxf(dl.w - sv.w*dl.w, 0.f);
        st4(skel + off + s*HWS + j*WW, sv);
      }
    }
  }
}

// edt step k: acc += cur ; nxt = minpool27(cur). 2 fields (4 vols), int offsets.
__device__ __forceinline__ void minpool_body(const float* __restrict__ cur,
                                             float* __restrict__ nxt,
                                             float* __restrict__ acc,
                                             int first, int tt, int k){
  if (g_nzM[k] == 0) return;
  int w0 = (tt & 31) << 2;
  int h0 = ((tt >> 5) & 31) << 2;
  int d  = (tt >> 10) & 63;
  int vb = tt >> 16;
  int sv = first ? ((vb < 2) ? vb : vb + 2) : vb;
  const float* sb = cur + sv*VOLSZ;
  int ob = vb*VOLSZ + d*HWS + h0*WW + w0;
  float4 o[4];
  box27_4bf<false>(sb, d, h0, w0, o);
  const float* p = sb + d*HWS + h0*WW + w0;
  float anymax = 0.f;
  #pragma unroll
  for (int j=0;j<4;j++){ anymax = fmaxf(anymax, h4max(o[j])); st4(nxt + ob + j*WW, o[j]); }
  if (first){
    #pragma unroll
    for (int j=0;j<4;j++) st4(acc + ob + j*WW, ld4(p + j*WW));
  } else {
    #pragma unroll
    for (int j=0;j<4;j++){
      float4 a = ld4(acc + ob + j*WW);
      float4 c = ld4(p + j*WW);
      a.x += c.x; a.y += c.y; a.z += c.z; a.w += c.w;
      st4(acc + ob + j*WW, a);
    }
  }
  if (anymax > 0.f) g_nzM[k+1] = 1;
}

// directional (Sobel) loss body — exact replica of reference kernel layout
__device__ __forceinline__ void dir_body(const float* __restrict__ net,
                                         const int* __restrict__ tgt, int t){
  int i = t << 2;
  int b = i >> 20;
  int r = i & (VOLSZ-1);
  int d = r >> 14, hh = (r >> 7) & 127, w0 = r & 127;
  const float* pb = net + i + b*VOLSZ;
  const int*   tb = tgt + i;
  float pgx[4]={0,0,0,0}, pgy[4]={0,0,0,0}, pgz[4]={0,0,0,0};
  float tgx[4]={0,0,0,0}, tgy[4]={0,0,0,0}, tgz[4]={0,0,0,0};
  #pragma unroll
  for (int dz=-1; dz<=1; ++dz){
    if ((unsigned)(d+dz) >= DD) continue;
    float cy = (dz==0) ? 2.f : 1.f;
    float cz = (float)dz;
    #pragma unroll
    for (int dy=-1; dy<=1; ++dy){
      if ((unsigned)(hh+dy) >= HH) continue;
      float cx = (dy==0) ? 2.f : 1.f;
      int off = dz*HWS + dy*WW;
      {
        const float* rp = pb + off;
        float vv[6];
        vv[0] = (w0 > 0) ? rp[-1] : 0.f;
        float4 v = ld4(rp);
        vv[1]=v.x; vv[2]=v.y; vv[3]=v.z; vv[4]=v.w;
        vv[5] = (w0 + 4 < WW) ? rp[4] : 0.f;
        #pragma unroll
        for (int k=0;k<4;k++){
          float dv = vv[k+2] - vv[k];
          float sv = vv[k] + 2.f*vv[k+1] + vv[k+2];
          pgx[k] += cx*dv; pgy[k] += cy*dv; pgz[k] += cz*sv;
        }
      }
      {
        const int* rp = tb + off;
        float vv[6];
        vv[0] = (w0 > 0) ? (float)rp[-1] : 0.f;
        int4 v = *reinterpret_cast<const int4*>(rp);
        vv[1]=(float)v.x; vv[2]=(float)v.y; vv[3]=(float)v.z; vv[4]=(float)v.w;
        vv[5] = (w0 + 4 < WW) ? (float)rp[4] : 0.f;
        #pragma unroll
        for (int k=0;k<4;k++){
          float dv = vv[k+2] - vv[k];
          float sv = vv[k] + 2.f*vv[k+1] + vv[k+2];
          tgx[k] += cx*dv; tgy[k] += cy*dv; tgz[k] += cz*sv;
        }
      }
    }
  }
  float acc = 0.f;
  #pragma unroll
  for (int k=0;k<4;k++){
    float np = sqrtf(pgx[k]*pgx[k] + pgy[k]*pgy[k] + pgz[k]*pgz[k]);
    float nt = sqrtf(tgx[k]*tgx[k] + tgy[k]*tgy[k] + tgz[k]*tgz[k]);
    float ip = 1.f / fmaxf(np, 1e-12f);
    float it = 1.f / fmaxf(nt, 1e-12f);
    float num = (pgx[k]*tgx[k] + pgy[k]*tgy[k] + pgz[k]*tgz[k]) * ip * it;
    float den = fmaxf((np*ip) * (nt*it), 1e-8f);
    acc += num / den;
  }
  block_add(&g_sums[S_DIR], acc);
}

// prob/y/hard + dice/CE/conn sums
__device__ __forceinline__ void init_body(const float* __restrict__ net,
                                          const int* __restrict__ tgt, int t){
  int i = t << 2;
  int b = i >> 20;
  float4 n0 = ld4(net + i + b*VOLSZ);
  float4 n1 = ld4(net + i + (b+1)*VOLSZ);
  int4   tg = *reinterpret_cast<const int4*>(tgt + i);
  float a[4] = {n0.x, n0.y, n0.z, n0.w};
  float c[4] = {n1.x, n1.y, n1.z, n1.w};
  int   l[4] = {tg.x, tg.y, tg.z, tg.w};
  float pv[4], yv[4], hv[4];
  float tp=0.f, fp=0.f, fn=0.f, ce=0.f, cn=0.f;
  #pragma unroll
  for (int k=0;k<4;k++){
    float y = (l[k] > 0) ? 1.f : 0.f;
    float p = 1.f / (1.f + expf(a[k] - c[k]));
    pv[k]=p; yv[k]=y; hv[k] = (p > 0.5f) ? 1.f : 0.f;
    tp += p*y; fp += p*(1.f-y); fn += (1.f-p)*y;
    float m = fmaxf(a[k], c[k]);
    float lse = m + logf(expf(a[k]-m) + expf(c[k]-m));
    ce += lse - ((l[k] > 0) ? c[k] : a[k]);
    cn += fabsf(((a[k] > 0.5f) ? 1.f : 0.f) - y)
        + fabsf(((c[k] > 0.5f) ? 1.f : 0.f) - y);
  }
  st4(g_SRC + i,          make_float4(yv[0],yv[1],yv[2],yv[3]));
  st4(g_SRC + NTOT + i,   make_float4(pv[0],pv[1],pv[2],pv[3]));
  st4(g_SRC + 2*NTOT + i, make_float4(hv[0],hv[1],hv[2],hv[3]));
  block_add(&g_sums[S_TP], tp);
  block_add(&g_sums[S_FP], fp);
  block_add(&g_sums[S_FN], fn);
  block_add(&g_sums[S_CE], ce);
  block_add(&g_sums[S_CONN], cn);
}

// ---------------- kernels ----------------
__global__ void zero_kernel(){
  int t = threadIdx.x;
  if (t < 14) g_sums[t] = 0.0;
  if (t < 2){
    g_maxT[t] = 0; g_maxP[t] = 0;
    g_minT[t] = 0x7f800000; g_minP[t] = 0x7f800000;
  }
  if (t < 17) g_nzM[t] = (t == 0) ? 1 : 0;
  if (t < 48){
    int f = t >> 4, s = t & 15;
    g_nzS[f][s] = (s == 0) ? 1 : 0;
  }
}

// fused [init | dir]
__global__ void __launch_bounds__(256) init_dir_kernel(const float* __restrict__ net,
                                                       const int* __restrict__ tgt){
  int bx = blockIdx.x, tid = threadIdx.x;
  if (bx < G_INIT) init_body(net, tgt, bx*256 + tid);
  else             dir_body(net, tgt, (bx - G_INIT)*256 + tid);
}

// L0: [erode gen0->1 | minpool step0]
__global__ void __launch_bounds__(256) combo_er0_mp0(const float* __restrict__ esrc,
                                                     float* __restrict__ edst,
                                                     float* __restrict__ mnxt,
                                                     float* __restrict__ macc){
  int bx = blockIdx.x, tid = threadIdx.x;
  if (bx < EB) erode_body(esrc, edst, bx*256 + tid, 0);
  else         minpool_body(esrc, mnxt, macc, 1, (bx - EB)*256 + tid, 0);
}

// pipelined: [dilate | erode | minpool]
__global__ void __launch_bounds__(256) combo_de_mp(const float* __restrict__ img,
                                                   const float* __restrict__ er,
                                                   float* __restrict__ skel,
                                                   int dinit, int dt,
                                                   float* __restrict__ edst, int et,
                                                   const float* __restrict__ mcur,
                                                   float* __restrict__ mnxt,
                                                   float* __restrict__ macc, int mk){
  int bx = blockIdx.x, tid = threadIdx.x;
  if (bx < DB)          dilate2_body(img, er, skel, dinit, bx*256 + tid, dt);
  else if (bx < DB+EB)  erode_body(er, edst, (bx - DB)*256 + tid, et);
  else                  minpool_body(mcur, mnxt, macc, 0, (bx - DB - EB)*256 + tid, mk);
}

// final dilate: [dilate | minpool]
__global__ void __launch_bounds__(256) combo_di_mp(const float* __restrict__ img,
                                                   const float* __restrict__ er,
                                                   float* __restrict__ skel,
                                                   int dinit, int dt,
                                                   const float* __restrict__ mcur,
                                                   float* __restrict__ mnxt,
                                                   float* __restrict__ macc, int mk){
  int bx = blockIdx.x, tid = threadIdx.x;
  if (bx < DB) dilate2_body(img, er, skel, dinit, bx*256 + tid, dt);
  else         minpool_body(mcur, mnxt, macc, 0, (bx - DB)*256 + tid, mk);
}

__global__ void __launch_bounds__(256) mp_only(const float* __restrict__ mcur,
                                               float* __restrict__ mnxt,
                                               float* __restrict__ macc, int mk){
  minpool_body(mcur, mnxt, macc, 0, blockIdx.x*256 + threadIdx.x, mk);
}

// per-batch max/min of skel_radius (vectorized x4)
__global__ void __launch_bounds__(256) r1_kernel(){
  int t = blockIdx.x*256 + threadIdx.x;
  int i = t << 2;
  int b = i >> 20;
  float4 y   = ld4(g_SRC + i);
  float4 p   = ld4(g_SRC + NTOT + i);
  float4 hd  = ld4(g_SRC + 2*NTOT + i);
  float4 st  = ld4(g_SK + i);
  float4 sph = ld4(g_SK + 2*NTOT + i);
  float4 aT  = ld4(g_ACC + i);
  float4 aP  = ld4(g_ACC + NTOT + i);
  float mxT, mnT, mxP, mnP;
  {
    float s0 = aT.x*y.x*st.x, s1 = aT.y*y.y*st.y, s2 = aT.z*y.z*st.z, s3 = aT.w*y.w*st.w;
    mxT = fmaxf(fmaxf(s0,s1), fmaxf(s2,s3));
    mnT = fminf(fminf(s0,s1), fminf(s2,s3));
    float b0 = (sph.x*p.x > 0.5f) ? 1.f : 0.f;
    float b1 = (sph.y*p.y > 0.5f) ? 1.f : 0.f;
    float b2 = (sph.z*p.z > 0.5f) ? 1.f : 0.f;
    float b3 = (sph.w*p.w > 0.5f) ? 1.f : 0.f;
    float q0 = aP.x*hd.x*b0, q1 = aP.y*hd.y*b1, q2 = aP.z*hd.z*b2, q3 = aP.w*hd.w*b3;
    mxP = fmaxf(fmaxf(q0,q1), fmaxf(q2,q3));
    mnP = fminf(fminf(q0,q1), fminf(q2,q3));
  }
  block_maxf(&g_maxT[b], mxT);
  block_minf(&g_minT[b], mnT);
  block_maxf(&g_maxP[b], mxP);
  block_minf(&g_minP[b], mnP);
}

// all union-loss + clDice sums (vectorized x4)
__global__ void __launch_bounds__(256) r2_kernel(){
  int t = blockIdx.x*256 + threadIdx.x;
  int i = t << 2;
  int b = i >> 20;
  float4 y4   = ld4(g_SRC + i);
  float4 p4   = ld4(g_SRC + NTOT + i);
  float4 hd4  = ld4(g_SRC + 2*NTOT + i);
  float4 st4v = ld4(g_SK + i);
  float4 sp4  = ld4(g_SK + NTOT + i);
  float4 sph4 = ld4(g_SK + 2*NTOT + i);
  float4 aT4  = ld4(g_ACC + i);
  float4 aP4  = ld4(g_ACC + NTOT + i);
  float rmaxT = fmaxf(__int_as_float(g_maxT[b]), 1.f);
  float rminT = fmaxf(__int_as_float(g_minT[b]), 1.f);
  float rmaxP = fmaxf(__int_as_float(g_maxP[b]), 1.f);
  float rminP = fmaxf(__int_as_float(g_minP[b]), 1.f);
  float irT = 1.f/rmaxT, irP = 1.f/rmaxP;

  float I1=0.f, U1=0.f, I2=0.f, U2=0.f, C1=0.f, C2=0.f, C3=0.f, C4=0.f;
  float yv[4]={y4.x,y4.y,y4.z,y4.w}, pv[4]={p4.x,p4.y,p4.z,p4.w};
  float hv[4]={hd4.x,hd4.y,hd4.z,hd4.w}, sv[4]={st4v.x,st4v.y,st4v.z,st4v.w};
  float spv[4]={sp4.x,sp4.y,sp4.z,sp4.w}, shv[4]={sph4.x,sph4.y,sph4.z,sph4.w};
  float atv[4]={aT4.x,aT4.y,aT4.z,aT4.w}, apv[4]={aP4.x,aP4.y,aP4.z,aP4.w};
  #pragma unroll
  for (int k=0;k<4;k++){
    float y=yv[k], p=pv[k], hd=hv[k], st=sv[k], sp=spv[k], sph=shv[k];
    float dT  = atv[k] * y;
    float srT = dT * st;
    float q_vl = fminf(dT, rmaxT) * irT * y;
    float t1 = (rmaxT - srT + rminT) * irT;
    float q_sl = t1*t1 * st * st;
    float dP  = apv[k] * hd;
    float sb  = (sph * p > 0.5f) ? 1.f : 0.f;
    float srP = dP * sb;
    float q_vp = fminf(dP, rmaxP) * irP * p;
    float t2 = (rmaxP - srP + rminP) * irP;
    float q_sp = t2*t2 * sb * (sph * p);
    I1 += q_sp * powf(q_sp + 1e-4f, 0.7f) * q_vl;
    U1 += q_sp * (0.1f*q_sp + 0.9f*q_vl);
    I2 += q_sl * powf(q_vp + 1e-4f, 0.7f) * q_sl;
    U2 += q_sl * (0.1f*q_vp + 0.9f*q_sl);
    C1 += sp*y; C2 += sp; C3 += st*p; C4 += st;
  }
  block_add(&g_sums[S_I1], I1);
  block_add(&g_sums[S_U1], U1);
  block_add(&g_sums[S_I2], I2);
  block_add(&g_sums[S_U2], U2);
  block_add(&g_sums[S_CL1], C1);
  block_add(&g_sums[S_CL2], C2);
  block_add(&g_sums[S_CL3], C3);
  block_add(&g_sums[S_CL4], C4);
}

__global__ void final_kernel(float* __restrict__ out){
  double tp = g_sums[S_TP], fp = g_sums[S_FP], fn = g_sums[S_FN];
  double dice = -((2.0*tp + 1e-5) / (2.0*tp + fp + fn + 1e-5));
  double ce   = g_sums[S_CE] / (double)NTOT;
  double conn = g_sums[S_CONN] / (2.0 * (double)NTOT);
  double dir  = 1.0 - g_sums[S_DIR] / (double)NTOT;
  double tprec = (g_sums[S_CL1] + 1.0) / (g_sums[S_CL2] + 1.0);
  double tsens = (g_sums[S_CL3] + 1.0) / (g_sums[S_CL4] + 1.0);
  double cl = 1.0 - 2.0*tprec*tsens / (tprec + tsens);
  double u  = (1.0 - (g_sums[S_I1] + 1.0) / (g_sums[S_U1] + 1.0))
            + (1.0 - (g_sums[S_I2] + 1.0) / (g_sums[S_U2] + 1.0));
  out[0] = (float)(dice + ce + cl + dir + conn + u);
}

// ---------------- host orchestration ----------------
extern "C" void kernel_launch(void* const* d_in, const int* in_sizes, int n_in,
                              void* d_out, int out_size){
  (void)in_sizes; (void)n_in; (void)out_size;
  const float* net = (const float*)d_in[0];
  const int*   tgt = (const int*)d_in[1];
  float* out = (float*)d_out;

  float *SRC,*SK,*B0,*B1,*B2,*MA,*MBp,*ACC;
  cudaGetSymbolAddress((void**)&SRC, g_SRC);
  cudaGetSymbolAddress((void**)&SK,  g_SK);
  cudaGetSymbolAddress((void**)&B0,  g_B0);
  cudaGetSymbolAddress((void**)&B1,  g_B1);
  cudaGetSymbolAddress((void**)&B2,  g_B2);
  cudaGetSymbolAddress((void**)&MA,  g_MA);
  cudaGetSymbolAddress((void**)&MBp, g_MB);
  cudaGetSymbolAddress((void**)&ACC, g_ACC);

  zero_kernel<<<1,64>>>();
  init_dir_kernel<<<G_INIT+DIRB,256>>>(net, tgt);

  float* sb3[3] = {B0, B1, B2};
  auto gbuf = [&](int g)->float*{ return sb3[(g-1)%3]; };
  float* mbufs[2] = {MA, MBp};

  combo_er0_mp0<<<EB+MB,256>>>(SRC, gbuf(1), MA, ACC);

  for (int k=1; k<=10; ++k){
    const float* img = (k==1) ? SRC : gbuf(k-1);
    combo_de_mp<<<DB+EB+MB,256>>>(img, gbuf(k), SK, (k==1)?1:0, k-1,
                                  gbuf(k+1), k,
                                  mbufs[(k+1)&1], mbufs[k&1], ACC, k);
  }
  combo_di_mp<<<DB+MB,256>>>(gbuf(10), gbuf(11), SK, 0, 10,
                             mbufs[(11+1)&1], mbufs[11&1], ACC, 11);
  for (int k=12; k<16; ++k)
    mp_only<<<MB,256>>>(mbufs[(k+1)&1], mbufs[k&1], ACC, k);

  r1_kernel<<<GS4,256>>>();
  r2_kernel<<<GS4,256>>>();
  final_kernel<<<1,1>>>(out);
}

// round 15
// speedup vs baseline: 1.2347x; 1.2347x over previous
#include <cuda_runtime.h>
#include <math.h>

// Dims per reference: B=2, C=2, D=64, H=128, W=128
#define DD 64
#define HH 128
#define WW 128
#define VOLSZ (DD*HH*WW)       // 2^20
#define NTOT  (2*VOLSZ)        // 2^21 (one "field" = 2 volumes)
#define HWS   (HH*WW)
#define G_INIT ((NTOT/4)/256)  // 2048
#define GS4    ((NTOT/4)/256)  // 2048

#define EB  768     // erode blocks: 3 fields, 4w x 4h x 2d tiles
#define DB  768     // dilate blocks
#define MB  1024    // minpool blocks: 2 fields, 4w x 4h x 1d tiles
#define DIRB 2048   // dir blocks

// ---------------- scratch ----------------
__device__ float g_SRC[3*NTOT];   // [Y | P | Hd]  (generation 0)
__device__ float g_SK [3*NTOT];   // [ST | SP | SPH]
__device__ float g_B0 [3*NTOT];   // skel generation rotation (3 bufs)
__device__ float g_B1 [3*NTOT];
__device__ float g_B2 [3*NTOT];
__device__ float g_MA [2*NTOT];   // edt ping
__device__ float g_MB [2*NTOT];   // edt pong
__device__ float g_ACC[2*NTOT];

__device__ double g_sums[14];
__device__ int g_maxT[2], g_minT[2], g_maxP[2], g_minP[2];

// nonzero flags: g_nzS[f][g] = "skel field f, erode generation I_g has any nonzero"
// g_nzM[k] = "EDT input to step k has any nonzero"
__device__ int g_nzS[3][16];
__device__ int g_nzM[17];

enum { S_TP=0, S_FP, S_FN, S_CE, S_CONN, S_DIR,
       S_CL1, S_CL2, S_CL3, S_CL4, S_I1, S_U1, S_I2, S_U2 };

// ---------------- helpers ----------------
__device__ __forceinline__ float4 ld4(const float* p){ return *reinterpret_cast<const float4*>(p); }
__device__ __forceinline__ void   st4(float* p, float4 v){ *reinterpret_cast<float4*>(p) = v; }
__device__ __forceinline__ float4 f4min(float4 a, float4 b){
  return make_float4(fminf(a.x,b.x), fminf(a.y,b.y), fminf(a.z,b.z), fminf(a.w,b.w));
}
__device__ __forceinline__ float4 f4max(float4 a, float4 b){
  return make_float4(fmaxf(a.x,b.x), fmaxf(a.y,b.y), fmaxf(a.z,b.z), fmaxf(a.w,b.w));
}
template<bool MX> __device__ __forceinline__ float opf(float a, float b){
  return MX ? fmaxf(a,b) : fminf(a,b);
}
template<bool MX> __device__ __forceinline__ float4 opf4(float4 a, float4 b){
  return MX ? f4max(a,b) : f4min(a,b);
}
__device__ __forceinline__ float4 selpad(float4 v, bool ok, float pad){
  return ok ? v : make_float4(pad,pad,pad,pad);
}
__device__ __forceinline__ float h4max(float4 v){
  return fmaxf(fmaxf(v.x,v.y), fmaxf(v.z,v.w));
}

template<bool MX>
__device__ __forceinline__ float4 rw3bf(const float* rp, bool okl, bool okr, bool rowok){
  const float pad = MX ? -1e30f : 1e30f;
  float  l = rp[okl ? -1 : 0];
  float  r = rp[okr ?  4 : 3];
  float4 v = ld4(rp);
  l = okl ? l : pad;
  r = okr ? r : pad;
  float4 o;
  o.x = opf<MX>(opf<MX>(l,  v.x), v.y);
  o.y = opf<MX>(opf<MX>(v.x,v.y), v.z);
  o.z = opf<MX>(opf<MX>(v.y,v.z), v.w);
  o.w = opf<MX>(opf<MX>(v.z,v.w), r);
  return selpad(o, rowok, pad);
}

// 3x3x3 box pool over 4x4 tile at depth d (branch-free)
template<bool MX>
__device__ __forceinline__ void box27_4bf(const float* vbase, int d, int h0, int w0,
                                          float4 out[4]){
  const float pad = MX ? -1e30f : 1e30f;
  const float4 P4 = make_float4(pad,pad,pad,pad);
  out[0]=out[1]=out[2]=out[3]=P4;
  bool okl = (w0 > 0), okr = (w0 + 4 < WW);
  #pragma unroll
  for (int pz=0; pz<3; ++pz){
    int dd = d - 1 + pz;
    bool zok = (unsigned)dd < DD;
    const float* pp = vbase + (zok ? dd : (dd < 0 ? 0 : DD-1))*HWS;
    float4 rw[6];
    #pragma unroll
    for (int jr=0; jr<6; ++jr){
      int hh = h0 - 1 + jr;
      bool ok = zok & ((unsigned)hh < HH);
      const float* rp = pp + (((unsigned)hh < HH) ? hh : (hh < 0 ? 0 : HH-1))*WW + w0;
      rw[jr] = rw3bf<MX>(rp, okl, okr, ok);
    }
    #pragma unroll
    for (int j=0;j<4;j++)
      out[j] = opf4<MX>(out[j], opf4<MX>(rw[j], opf4<MX>(rw[j+1], rw[j+2])));
  }
}

// ---------------- reductions ----------------
__device__ __forceinline__ float warp_sum(float v){
  #pragma unroll
  for (int o=16; o; o>>=1) v += __shfl_down_sync(0xffffffffu, v, o);
  return v;
}
__device__ __forceinline__ void block_add(double* dst, float v){
  __shared__ float sh[8];
  v = warp_sum(v);
  if ((threadIdx.x & 31) == 0) sh[threadIdx.x >> 5] = v;
  __syncthreads();
  if (threadIdx.x == 0){
    float t = sh[0]+sh[1]+sh[2]+sh[3]+sh[4]+sh[5]+sh[6]+sh[7];
    atomicAdd(dst, (double)t);
  }
  __syncthreads();
}
__device__ __forceinline__ void block_maxf(int* dst, float v){
  __shared__ float sh[8];
  #pragma unroll
  for (int o=16; o; o>>=1) v = fmaxf(v, __shfl_down_sync(0xffffffffu, v, o));
  if ((threadIdx.x & 31) == 0) sh[threadIdx.x >> 5] = v;
  __syncthreads();
  if (threadIdx.x == 0){
    float m = sh[0];
    #pragma unroll
    for (int k=1;k<8;k++) m = fmaxf(m, sh[k]);
    atomicMax(dst, __float_as_int(m));
  }
  __syncthreads();
}
__device__ __forceinline__ void block_minf(int* dst, float v){
  __shared__ float sh[8];
  #pragma unroll
  for (int o=16; o; o>>=1) v = fminf(v, __shfl_down_sync(0xffffffffu, v, o));
  if ((threadIdx.x & 31) == 0) sh[threadIdx.x >> 5] = v;
  __syncthreads();
  if (threadIdx.x == 0){
    float m = sh[0];
    #pragma unroll
    for (int k=1;k<8;k++) m = fminf(m, sh[k]);
    atomicMin(dst, __float_as_int(m));
  }
  __syncthreads();
}

// ---------------- bodies ----------------
// soft_erode (7-pt cross), 4w x 4h x 2d tile. et = generation of src (I_et).
__device__ __forceinline__ void erode_body(const float* __restrict__ src,
                                           float* __restrict__ dst, int tt, int et){
  int vb = tt >> 15;
  int f  = vb >> 1;
  if (g_nzS[f][et] == 0) return;
  int w0 = (tt & 31) << 2;
  int h0 = ((tt >> 5) & 31) << 2;
  int d0 = ((tt >> 10) & 31) << 1;
  const float* vbase = src + (long)vb*VOLSZ;
  const float INF = 1e30f;

  float4 C[4][4];
  #pragma unroll
  for (int pz=0; pz<4; ++pz){
    int dd = d0 - 1 + pz;
    bool zok = (unsigned)dd < DD;
    const float* pp = vbase + (zok ? dd : (dd < 0 ? 0 : DD-1))*HWS + h0*WW + w0;
    #pragma unroll
    for (int j=0;j<4;j++)
      C[pz][j] = selpad(ld4(pp + j*WW), zok, INF);
  }
  float4 HB[2][2];
  bool okm = (h0 > 0), okp = (h0 + 4 < HH);
  #pragma unroll
  for (int s=0;s<2;s++){
    const float* pp = vbase + (d0+s)*HWS;
    HB[s][0] = selpad(ld4(pp + (okm ? h0-1 : 0)*WW + w0), okm, INF);
    HB[s][1] = selpad(ld4(pp + (okp ? h0+4 : HH-1)*WW + w0), okp, INF);
  }
  float L[2][4], R[2][4];
  bool okl = (w0 > 0), okr = (w0 + 4 < WW);
  #pragma unroll
  for (int s=0;s<2;s++){
    const float* pp = vbase + (d0+s)*HWS + h0*WW + w0;
    #pragma unroll
    for (int j=0;j<4;j++){
      float l = pp[j*WW + (okl ? -1 : 0)];
      float r = pp[j*WW + (okr ?  4 : 3)];
      L[s][j] = okl ? l : INF;
      R[s][j] = okr ? r : INF;
    }
  }
  float* obase = dst + (long)vb*VOLSZ + d0*HWS + h0*WW + w0;
  float anymax = 0.f;
  #pragma unroll
  for (int s=0;s<2;s++){
    #pragma unroll
    for (int j=0;j<4;j++){
      float4 v = C[s+1][j];
      float4 w3;
      w3.x = fminf(fminf(L[s][j], v.x), v.y);
      w3.y = fminf(fminf(v.x, v.y), v.z);
      w3.z = fminf(fminf(v.y, v.z), v.w);
      w3.w = fminf(fminf(v.z, v.w), R[s][j]);
      float4 up = (j==0) ? HB[s][0] : C[s+1][j-1];
      float4 dn = (j==3) ? HB[s][1] : C[s+1][j+1];
      float4 m = f4min(w3, f4min(up, dn));
      m = f4min(m, f4min(C[s][j], C[s+2][j]));
      anymax = fmaxf(anymax, h4max(m));
      st4(obase + s*HWS + j*WW, m);
    }
  }
  if (anymax > 0.f) g_nzS[f][et+1] = 1;   // benign race
}

// dilate27(er) + skel update, 4w x 4h x 2d tile (single-pass, separable h-max)
__device__ __forceinline__ void dilate2_body(const float* __restrict__ img,
                                             const float* __restrict__ er,
                                             float* __restrict__ skel,
                                             int init, int tt, int dt){
  int vb = tt >> 15;
  int f  = vb >> 1;
  if (g_nzS[f][dt] == 0) return;
  int w0 = (tt & 31) << 2;
  int h0 = ((tt >> 5) & 31) << 2;
  int d0 = ((tt >> 10) & 31) << 1;
  const float* ebase = er + (long)vb*VOLSZ;
  bool okl = (w0 > 0), okr = (w0 + 4 < WW);
  const float4 N4 = make_float4(-1e30f,-1e30f,-1e30f,-1e30f);
  float4 out[2][4];
  #pragma unroll
  for (int j=0;j<4;j++){ out[0][j]=N4; out[1][j]=N4; }
  bool er_nz = (g_nzS[f][dt+1] != 0);
  if (er_nz){
    #pragma unroll
    for (int pz=0; pz<4; ++pz){
      int dd = d0 - 1 + pz;
      bool zok = (unsigned)dd < DD;
      const float* pp = ebase + (zok ? dd : (dd < 0 ? 0 : DD-1))*HWS;
      float4 rw[6];
      #pragma unroll
      for (int jr=0; jr<6; ++jr){
        int hh = h0 - 1 + jr;
        bool ok = zok & ((unsigned)hh < HH);
        const float* rp = pp + (((unsigned)hh < HH) ? hh : (hh < 0 ? 0 : HH-1))*WW + w0;
        rw[jr] = rw3bf<true>(rp, okl, okr, ok);
      }
      float4 mh[4];
      #pragma unroll
      for (int j=0;j<4;j++) mh[j] = f4max(rw[j], f4max(rw[j+1], rw[j+2]));
      if (pz <= 2){
        #pragma unroll
        for (int j=0;j<4;j++) out[0][j] = f4max(out[0][j], mh[j]);
      }
      if (pz >= 1){
        #pragma unroll
        for (int j=0;j<4;j++) out[1][j] = f4max(out[1][j], mh[j]);
      }
    }
  } else {
    #pragma unroll
    for (int j=0;j<4;j++){
      out[0][j] = make_float4(0.f,0.f,0.f,0.f);
      out[1][j] = make_float4(0.f,0.f,0.f,0.f);
    }
  }
  long off = (long)vb*VOLSZ + d0*HWS + h0*WW + w0;
  #pragma unroll
  for (int s=0;s<2;s++){
    #pragma unroll
    for (int j=0;j<4;j++){
      float4 im = ld4(img + off + s*HWS + j*WW);
      float4 o = out[s][j];
      float4 dl = make_float4(fmaxf(im.x-o.x,0.f), fmaxf(im.y-o.y,0.f),
                              fmaxf(im.z-o.z,0.f), fmaxf(im.w-o.w,0.f));
      if (init){
        st4(skel + off + s*HWS + j*WW, dl);
      } else {
        float4 sv = ld4(skel + off + s*HWS + j*WW);
        sv.x += fmaxf(dl.x - sv.x*dl.x, 0.f);
        sv.y += fmaxf(dl.y - sv.y*dl.y, 0.f);
        sv.z += fmaxf(dl.z - sv.z*dl.z, 0.f);
        sv.w += fmaxf(dl.w - sv.w*dl.w, 0.f);
        st4(skel + off + s*HWS + j*WW, sv);
      }
    }
  }
}

// edt step k: acc += cur ; nxt = minpool27(cur). 2 fields (4 vols).
__device__ __forceinline__ void minpool_body(const float* __restrict__ cur,
                                             float* __restrict__ nxt,
                                             float* __restrict__ acc,
                                             int first, int tt, int k){
  if (g_nzM[k] == 0) return;
  int w0 = (tt & 31) << 2;
  int h0 = ((tt >> 5) & 31) << 2;
  int d  = (tt >> 10) & 63;
  int vb = tt >> 16;
  int sv = first ? ((vb < 2) ? vb : vb + 2) : vb;   // {Y0,Y1,Hd0,Hd1} in SRC
  const float* sb = cur + (long)sv*VOLSZ;
  long ob = (long)vb*VOLSZ + d*HWS + h0*WW + w0;
  float4 o[4];
  box27_4bf<false>(sb, d, h0, w0, o);
  const float* p = sb + d*HWS + h0*WW + w0;
  float anymax = 0.f;
  #pragma unroll
  for (int j=0;j<4;j++){ anymax = fmaxf(anymax, h4max(o[j])); st4(nxt + ob + j*WW, o[j]); }
  if (first){
    #pragma unroll
    for (int j=0;j<4;j++) st4(acc + ob + j*WW, ld4(p + j*WW));
  } else {
    #pragma unroll
    for (int j=0;j<4;j++){
      float4 a = ld4(acc + ob + j*WW);
      float4 c = ld4(p + j*WW);
      a.x += c.x; a.y += c.y; a.z += c.z; a.w += c.w;
      st4(acc + ob + j*WW, a);
    }
  }
  if (anymax > 0.f) g_nzM[k+1] = 1;
}

// directional (Sobel) loss body — exact replica of reference kernel layout
__device__ __forceinline__ void dir_body(const float* __restrict__ net,
                                         const int* __restrict__ tgt, int t){
  int i = t << 2;
  int b = i >> 20;
  int r = i & (VOLSZ-1);
  int d = r >> 14, hh = (r >> 7) & 127, w0 = r & 127;
  const float* pb = net + i + b*VOLSZ;
  const int*   tb = tgt + i;
  float pgx[4]={0,0,0,0}, pgy[4]={0,0,0,0}, pgz[4]={0,0,0,0};
  float tgx[4]={0,0,0,0}, tgy[4]={0,0,0,0}, tgz[4]={0,0,0,0};
  #pragma unroll
  for (int dz=-1; dz<=1; ++dz){
    if ((unsigned)(d+dz) >= DD) continue;
    float cy = (dz==0) ? 2.f : 1.f;
    float cz = (float)dz;
    #pragma unroll
    for (int dy=-1; dy<=1; ++dy){
      if ((unsigned)(hh+dy) >= HH) continue;
      float cx = (dy==0) ? 2.f : 1.f;
      int off = dz*HWS + dy*WW;
      {
        const float* rp = pb + off;
        float vv[6];
        vv[0] = (w0 > 0) ? rp[-1] : 0.f;
        float4 v = ld4(rp);
        vv[1]=v.x; vv[2]=v.y; vv[3]=v.z; vv[4]=v.w;
        vv[5] = (w0 + 4 < WW) ? rp[4] : 0.f;
        #pragma unroll
        for (int k=0;k<4;k++){
          float dv = vv[k+2] - vv[k];
          float sv = vv[k] + 2.f*vv[k+1] + vv[k+2];
          pgx[k] += cx*dv; pgy[k] += cy*dv; pgz[k] += cz*sv;
        }
      }
      {
        const int* rp = tb + off;
        float vv[6];
        vv[0] = (w0 > 0) ? (float)rp[-1] : 0.f;
        int4 v = *reinterpret_cast<const int4*>(rp);
        vv[1]=(float)v.x; vv[2]=(float)v.y; vv[3]=(float)v.z; vv[4]=(float)v.w;
        vv[5] = (w0 + 4 < WW) ? (float)rp[4] : 0.f;
        #pragma unroll
        for (int k=0;k<4;k++){
          float dv = vv[k+2] - vv[k];
          float sv = vv[k] + 2.f*vv[k+1] + vv[k+2];
          tgx[k] += cx*dv; tgy[k] += cy*dv; tgz[k] += cz*sv;
        }
      }
    }
  }
  float acc = 0.f;
  #pragma unroll
  for (int k=0;k<4;k++){
    float np = sqrtf(pgx[k]*pgx[k] + pgy[k]*pgy[k] + pgz[k]*pgz[k]);
    float nt = sqrtf(tgx[k]*tgx[k] + tgy[k]*tgy[k] + tgz[k]*tgz[k]);
    float ip = 1.f / fmaxf(np, 1e-12f);
    float it = 1.f / fmaxf(nt, 1e-12f);
    float num = (pgx[k]*tgx[k] + pgy[k]*tgy[k] + pgz[k]*tgz[k]) * ip * it;
    float den = fmaxf((np*ip) * (nt*it), 1e-8f);
    acc += num / den;
  }
  block_add(&g_sums[S_DIR], acc);
}

// prob/y/hard + dice/CE/conn sums
__device__ __forceinline__ void init_body(const float* __restrict__ net,
                                          const int* __restrict__ tgt, int t){
  int i = t << 2;
  int b = i >> 20;
  float4 n0 = ld4(net + i + b*VOLSZ);
  float4 n1 = ld4(net + i + (b+1)*VOLSZ);
  int4   tg = *reinterpret_cast<const int4*>(tgt + i);
  float a[4] = {n0.x, n0.y, n0.z, n0.w};
  float c[4] = {n1.x, n1.y, n1.z, n1.w};
  int   l[4] = {tg.x, tg.y, tg.z, tg.w};
  float pv[4], yv[4], hv[4];
  float tp=0.f, fp=0.f, fn=0.f, ce=0.f, cn=0.f;
  #pragma unroll
  for (int k=0;k<4;k++){
    float y = (l[k] > 0) ? 1.f : 0.f;
    float p = 1.f / (1.f + expf(a[k] - c[k]));
    pv[k]=p; yv[k]=y; hv[k] = (p > 0.5f) ? 1.f : 0.f;
    tp += p*y; fp += p*(1.f-y); fn += (1.f-p)*y;
    float m = fmaxf(a[k], c[k]);
    float lse = m + logf(expf(a[k]-m) + expf(c[k]-m));
    ce += lse - ((l[k] > 0) ? c[k] : a[k]);
    cn += fabsf(((a[k] > 0.5f) ? 1.f : 0.f) - y)
        + fabsf(((c[k] > 0.5f) ? 1.f : 0.f) - y);
  }
  st4(g_SRC + i,          make_float4(yv[0],yv[1],yv[2],yv[3]));
  st4(g_SRC + NTOT + i,   make_float4(pv[0],pv[1],pv[2],pv[3]));
  st4(g_SRC + 2*NTOT + i, make_float4(hv[0],hv[1],hv[2],hv[3]));
  block_add(&g_sums[S_TP], tp);
  block_add(&g_sums[S_FP], fp);
  block_add(&g_sums[S_FN], fn);
  block_add(&g_sums[S_CE], ce);
  block_add(&g_sums[S_CONN], cn);
}

// ---------------- kernels ----------------
__global__ void zero_kernel(){
  int t = threadIdx.x;
  if (t < 14) g_sums[t] = 0.0;
  if (t < 2){
    g_maxT[t] = 0; g_maxP[t] = 0;
    g_minT[t] = 0x7f800000; g_minP[t] = 0x7f800000;
  }
  if (t < 17) g_nzM[t] = (t == 0) ? 1 : 0;
  if (t < 48){
    int f = t >> 4, s = t & 15;
    g_nzS[f][s] = (s == 0) ? 1 : 0;
  }
}

// fused [init | dir] — both consume only (net, tgt); shares input lines in L2
__global__ void __launch_bounds__(256) init_dir_kernel(const float* __restrict__ net,
                                                       const int* __restrict__ tgt){
  int bx = blockIdx.x, tid = threadIdx.x;
  if (bx < G_INIT) init_body(net, tgt, bx*256 + tid);
  else             dir_body(net, tgt, (bx - G_INIT)*256 + tid);
}

// L0: [erode gen0->1 | minpool step0]
__global__ void __launch_bounds__(256) combo_er0_mp0(const float* __restrict__ esrc,
                                                     float* __restrict__ edst,
                                                     float* __restrict__ mnxt,
                                                     float* __restrict__ macc){
  int bx = blockIdx.x, tid = threadIdx.x;
  if (bx < EB) erode_body(esrc, edst, bx*256 + tid, 0);
  else         minpool_body(esrc, mnxt, macc, 1, (bx - EB)*256 + tid, 0);
}

// pipelined: [dilate(img=gen k-1, er=gen k) | erode(gen k -> gen k+1) | minpool k]
__global__ void __launch_bounds__(256) combo_de_mp(const float* __restrict__ img,
                                                   const float* __restrict__ er,
                                                   float* __restrict__ skel,
                                                   int dinit, int dt,
                                                   float* __restrict__ edst, int et,
                                                   const float* __restrict__ mcur,
                                                   float* __restrict__ mnxt,
                                                   float* __restrict__ macc, int mk){
  int bx = blockIdx.x, tid = threadIdx.x;
  if (bx < DB)          dilate2_body(img, er, skel, dinit, bx*256 + tid, dt);
  else if (bx < DB+EB)  erode_body(er, edst, (bx - DB)*256 + tid, et);
  else                  minpool_body(mcur, mnxt, macc, 0, (bx - DB - EB)*256 + tid, mk);
}

// final dilate: [dilate | minpool]
__global__ void __launch_bounds__(256) combo_di_mp(const float* __restrict__ img,
                                                   const float* __restrict__ er,
                                                   float* __restrict__ skel,
                                                   int dinit, int dt,
                                                   const float* __restrict__ mcur,
                                                   float* __restrict__ mnxt,
                                                   float* __restrict__ macc, int mk){
  int bx = blockIdx.x, tid = threadIdx.x;
  if (bx < DB) dilate2_body(img, er, skel, dinit, bx*256 + tid, dt);
  else         minpool_body(mcur, mnxt, macc, 0, (bx - DB)*256 + tid, mk);
}

// tail minpool steps (normally early-exit)
__global__ void __launch_bounds__(256) mp_only(const float* __restrict__ mcur,
                                               float* __restrict__ mnxt,
                                               float* __restrict__ macc, int mk){
  minpool_body(mcur, mnxt, macc, 0, blockIdx.x*256 + threadIdx.x, mk);
}

// per-batch max/min of skel_radius (vectorized x4)
__global__ void __launch_bounds__(256) r1_kernel(){
  int t = blockIdx.x*256 + threadIdx.x;
  int i = t << 2;
  int b = i >> 20;
  float4 y   = ld4(g_SRC + i);
  float4 p   = ld4(g_SRC + NTOT + i);
  float4 hd  = ld4(g_SRC + 2*NTOT + i);
  float4 st  = ld4(g_SK + i);
  float4 sph = ld4(g_SK + 2*NTOT + i);
  float4 aT  = ld4(g_ACC + i);
  float4 aP  = ld4(g_ACC + NTOT + i);
  float mxT, mnT, mxP, mnP;
  {
    float s0 = aT.x*y.x*st.x, s1 = aT.y*y.y*st.y, s2 = aT.z*y.z*st.z, s3 = aT.w*y.w*st.w;
    mxT = fmaxf(fmaxf(s0,s1), fmaxf(s2,s3));
    mnT = fminf(fminf(s0,s1), fminf(s2,s3));
    float b0 = (sph.x*p.x > 0.5f) ? 1.f : 0.f;
    float b1 = (sph.y*p.y > 0.5f) ? 1.f : 0.f;
    float b2 = (sph.z*p.z > 0.5f) ? 1.f : 0.f;
    float b3 = (sph.w*p.w > 0.5f) ? 1.f : 0.f;
    float q0 = aP.x*hd.x*b0, q1 = aP.y*hd.y*b1, q2 = aP.z*hd.z*b2, q3 = aP.w*hd.w*b3;
    mxP = fmaxf(fmaxf(q0,q1), fmaxf(q2,q3));
    mnP = fminf(fminf(q0,q1), fminf(q2,q3));
  }
  block_maxf(&g_maxT[b], mxT);
  block_minf(&g_minT[b], mnT);
  block_maxf(&g_maxP[b], mxP);
  block_minf(&g_minP[b], mnP);
}

// all union-loss + clDice sums (vectorized x4)
__global__ void __launch_bounds__(256) r2_kernel(){
  int t = blockIdx.x*256 + threadIdx.x;
  int i = t << 2;
  int b = i >> 20;
  float4 y4   = ld4(g_SRC + i);
  float4 p4   = ld4(g_SRC + NTOT + i);
  float4 hd4  = ld4(g_SRC + 2*NTOT + i);
  float4 st4v = ld4(g_SK + i);
  float4 sp4  = ld4(g_SK + NTOT + i);
  float4 sph4 = ld4(g_SK + 2*NTOT + i);
  float4 aT4  = ld4(g_ACC + i);
  float4 aP4  = ld4(g_ACC + NTOT + i);
  float rmaxT = fmaxf(__int_as_float(g_maxT[b]), 1.f);
  float rminT = fmaxf(__int_as_float(g_minT[b]), 1.f);
  float rmaxP = fmaxf(__int_as_float(g_maxP[b]), 1.f);
  float rminP = fmaxf(__int_as_float(g_minP[b]), 1.f);
  float irT = 1.f/rmaxT, irP = 1.f/rmaxP;

  float I1=0.f, U1=0.f, I2=0.f, U2=0.f, C1=0.f, C2=0.f, C3=0.f, C4=0.f;
  float yv[4]={y4.x,y4.y,y4.z,y4.w}, pv[4]={p4.x,p4.y,p4.z,p4.w};
  float hv[4]={hd4.x,hd4.y,hd4.z,hd4.w}, sv[4]={st4v.x,st4v.y,st4v.z,st4v.w};
  float spv[4]={sp4.x,sp4.y,sp4.z,sp4.w}, shv[4]={sph4.x,sph4.y,sph4.z,sph4.w};
  float atv[4]={aT4.x,aT4.y,aT4.z,aT4.w}, apv[4]={aP4.x,aP4.y,aP4.z,aP4.w};
  #pragma unroll
  for (int k=0;k<4;k++){
    float y=yv[k], p=pv[k], hd=hv[k], st=sv[k], sp=spv[k], sph=shv[k];
    float dT  = atv[k] * y;
    float srT = dT * st;
    float q_vl = fminf(dT, rmaxT) * irT * y;
    float t1 = (rmaxT - srT + rminT) * irT;
    float q_sl = t1*t1 * st * st;
    float dP  = apv[k] * hd;
    float sb  = (sph * p > 0.5f) ? 1.f : 0.f;
    float srP = dP * sb;
    float q_vp = fminf(dP, rmaxP) * irP * p;
    float t2 = (rmaxP - srP + rminP) * irP;
    float q_sp = t2*t2 * sb * (sph * p);
    I1 += q_sp * powf(q_sp + 1e-4f, 0.7f) * q_vl;
    U1 += q_sp * (0.1f*q_sp + 0.9f*q_vl);
    I2 += q_sl * powf(q_vp + 1e-4f, 0.7f) * q_sl;
    U2 += q_sl * (0.1f*q_vp + 0.9f*q_sl);
    C1 += sp*y; C2 += sp; C3 += st*p; C4 += st;
  }
  block_add(&g_sums[S_I1], I1);
  block_add(&g_sums[S_U1], U1);
  block_add(&g_sums[S_I2], I2);
  block_add(&g_sums[S_U2], U2);
  block_add(&g_sums[S_CL1], C1);
  block_add(&g_sums[S_CL2], C2);
  block_add(&g_sums[S_CL3], C3);
  block_add(&g_sums[S_CL4], C4);
}

__global__ void final_kernel(float* __restrict__ out){
  double tp = g_sums[S_TP], fp = g_sums[S_FP], fn = g_sums[S_FN];
  double dice = -((2.0*tp + 1e-5) / (2.0*tp + fp + fn + 1e-5));
  double ce   = g_sums[S_CE] / (double)NTOT;
  double conn = g_sums[S_CONN] / (2.0 * (double)NTOT);
  double dir  = 1.0 - g_sums[S_DIR] / (double)NTOT;
  double tprec = (g_sums[S_CL1] + 1.0) / (g_sums[S_CL2] + 1.0);
  double tsens = (g_sums[S_CL3] + 1.0) / (g_sums[S_CL4] + 1.0);
  double cl = 1.0 - 2.0*tprec*tsens / (tprec + tsens);
  double u  = (1.0 - (g_sums[S_I1] + 1.0) / (g_sums[S_U1] + 1.0))
            + (1.0 - (g_sums[S_I2] + 1.0) / (g_sums[S_U2] + 1.0));
  out[0] = (float)(dice + ce + cl + dir + conn + u);
}

// ---------------- host orchestration ----------------
extern "C" void kernel_launch(void* const* d_in, const int* in_sizes, int n_in,
                              void* d_out, int out_size){
  (void)in_sizes; (void)n_in; (void)out_size;
  const float* net = (const float*)d_in[0];
  const int*   tgt = (const int*)d_in[1];
  float* out = (float*)d_out;

  float *SRC,*SK,*B0,*B1,*B2,*MA,*MBp,*ACC;
  cudaGetSymbolAddress((void**)&SRC, g_SRC);
  cudaGetSymbolAddress((void**)&SK,  g_SK);
  cudaGetSymbolAddress((void**)&B0,  g_B0);
  cudaGetSymbolAddress((void**)&B1,  g_B1);
  cudaGetSymbolAddress((void**)&B2,  g_B2);
  cudaGetSymbolAddress((void**)&MA,  g_MA);
  cudaGetSymbolAddress((void**)&MBp, g_MB);
  cudaGetSymbolAddress((void**)&ACC, g_ACC);

  zero_kernel<<<1,64>>>();
  init_dir_kernel<<<G_INIT+DIRB,256>>>(net, tgt);

  // skel generation buffers: gen0 = SRC, gen g>=1 lives in sb[(g-1)%3]
  float* sb3[3] = {B0, B1, B2};
  auto gbuf = [&](int g)->float*{ return sb3[(g-1)%3]; };
  // EDT ping-pong: step0 writes MA; step k>=1 reads mbufs[(k+1)&1], writes mbufs[k&1]
  float* mbufs[2] = {MA, MBp};

  combo_er0_mp0<<<EB+MB,256>>>(SRC, gbuf(1), MA, ACC);

  for (int k=1; k<=10; ++k){
    const float* img = (k==1) ? SRC : gbuf(k-1);
    combo_de_mp<<<DB+EB+MB,256>>>(img, gbuf(k), SK, (k==1)?1:0, k-1,
                                  gbuf(k+1), k,
                                  mbufs[(k+1)&1], mbufs[k&1], ACC, k);
  }
  combo_di_mp<<<DB+MB,256>>>(gbuf(10), gbuf(11), SK, 0, 10,
                             mbufs[(11+1)&1], mbufs[11&1], ACC, 11);
  for (int k=12; k<16; ++k)
    mp_only<<<MB,256>>>(mbufs[(k+1)&1], mbufs[k&1], ACC, k);

  r1_kernel<<<GS4,256>>>();
  r2_kernel<<<GS4,256>>>();
  final_kernel<<<1,1>>>(out);
}

// round 16
// speedup vs baseline: 1.2645x; 1.0241x over previous
#include <cuda_runtime.h>
#include <math.h>

// Dims per reference: B=2, C=2, D=64, H=128, W=128
#define DD 64
#define HH 128
#define WW 128
#define VOLSZ (DD*HH*WW)       // 2^20
#define NTOT  (2*VOLSZ)        // 2^21 (one "field" = 2 volumes)
#define HWS   (HH*WW)
#define G_INIT ((NTOT/4)/256)  // 2048
#define GS4    ((NTOT/4)/256)  // 2048

#define EB  768     // erode blocks: 3 fields, 4w x 4h x 2d tiles
#define DB  768     // dilate blocks
#define MB  1024    // minpool blocks: 2 fields, 4w x 4h x 1d tiles
#define DIRB 2048   // dir blocks

// ---------------- scratch ----------------
__device__ float g_SRC[3*NTOT];   // [Y | P | Hd]  (generation 0)
__device__ float g_SK [3*NTOT];   // [ST | SP | SPH]
__device__ float g_B0 [3*NTOT];   // skel generation rotation (3 bufs)
__device__ float g_B1 [3*NTOT];
__device__ float g_B2 [3*NTOT];
__device__ float g_MA [2*NTOT];   // edt ping
__device__ float g_MB [2*NTOT];   // edt pong
__device__ float g_ACC[2*NTOT];

__device__ double g_sums[14];
__device__ int g_maxT[2], g_minT[2], g_maxP[2], g_minP[2];

// nonzero flags
__device__ int g_nzS[3][16];
__device__ int g_nzM[17];

enum { S_TP=0, S_FP, S_FN, S_CE, S_CONN, S_DIR,
       S_CL1, S_CL2, S_CL3, S_CL4, S_I1, S_U1, S_I2, S_U2 };

// ---------------- helpers ----------------
__device__ __forceinline__ float4 ld4(const float* p){ return *reinterpret_cast<const float4*>(p); }
__device__ __forceinline__ void   st4(float* p, float4 v){ *reinterpret_cast<float4*>(p) = v; }
__device__ __forceinline__ float4 f4min(float4 a, float4 b){
  return make_float4(fminf(a.x,b.x), fminf(a.y,b.y), fminf(a.z,b.z), fminf(a.w,b.w));
}
__device__ __forceinline__ float4 f4max(float4 a, float4 b){
  return make_float4(fmaxf(a.x,b.x), fmaxf(a.y,b.y), fmaxf(a.z,b.z), fmaxf(a.w,b.w));
}
template<bool MX> __device__ __forceinline__ float opf(float a, float b){
  return MX ? fmaxf(a,b) : fminf(a,b);
}
template<bool MX> __device__ __forceinline__ float4 opf4(float4 a, float4 b){
  return MX ? f4max(a,b) : f4min(a,b);
}
__device__ __forceinline__ float4 selpad(float4 v, bool ok, float pad){
  return ok ? v : make_float4(pad,pad,pad,pad);
}
__device__ __forceinline__ float h4max(float4 v){
  return fmaxf(fmaxf(v.x,v.y), fmaxf(v.z,v.w));
}

// warp-shuffle halos: lane == w-group (w0 = 4*lane spans the 128-wide row).
// left halo = lane-1's v.w ; right halo = lane+1's v.x ; edges -> pad.
__device__ __forceinline__ float shleft(float vw, float pad){
  float l = __shfl_up_sync(0xffffffffu, vw, 1);
  return ((threadIdx.x & 31) == 0) ? pad : l;
}
__device__ __forceinline__ float shright(float vx, float pad){
  float r = __shfl_down_sync(0xffffffffu, vx, 1);
  return ((threadIdx.x & 31) == 31) ? pad : r;
}

// 3-wide window over 4 consecutive w-outputs; halos via shfl (no scalar loads).
// Must be called by all 32 lanes (converged).
template<bool MX>
__device__ __forceinline__ float4 rw3s(const float* rp, bool rowok){
  const float pad = MX ? -1e30f : 1e30f;
  float4 v = ld4(rp);
  float  l = shleft(v.w, pad);
  float  r = shright(v.x, pad);
  float4 o;
  o.x = opf<MX>(opf<MX>(l,  v.x), v.y);
  o.y = opf<MX>(opf<MX>(v.x,v.y), v.z);
  o.z = opf<MX>(opf<MX>(v.y,v.z), v.w);
  o.w = opf<MX>(opf<MX>(v.z,v.w), r);
  return selpad(o, rowok, pad);
}

// 3x3x3 box pool over 4x4 tile at depth d (branch-free, shfl halos)
template<bool MX>
__device__ __forceinline__ void box27_4s(const float* vbase, int d, int h0, int w0,
                                         float4 out[4]){
  const float pad = MX ? -1e30f : 1e30f;
  const float4 P4 = make_float4(pad,pad,pad,pad);
  out[0]=out[1]=out[2]=out[3]=P4;
  #pragma unroll
  for (int pz=0; pz<3; ++pz){
    int dd = d - 1 + pz;
    bool zok = (unsigned)dd < DD;
    const float* pp = vbase + (zok ? dd : (dd < 0 ? 0 : DD-1))*HWS;
    float4 rw[6];
    #pragma unroll
    for (int jr=0; jr<6; ++jr){
      int hh = h0 - 1 + jr;
      bool ok = zok & ((unsigned)hh < HH);
      const float* rp = pp + (((unsigned)hh < HH) ? hh : (hh < 0 ? 0 : HH-1))*WW + w0;
      rw[jr] = rw3s<MX>(rp, ok);
    }
    #pragma unroll
    for (int j=0;j<4;j++)
      out[j] = opf4<MX>(out[j], opf4<MX>(rw[j], opf4<MX>(rw[j+1], rw[j+2])));
  }
}

// ---------------- reductions ----------------
__device__ __forceinline__ float warp_sum(float v){
  #pragma unroll
  for (int o=16; o; o>>=1) v += __shfl_down_sync(0xffffffffu, v, o);
  return v;
}
__device__ __forceinline__ void block_add(double* dst, float v){
  __shared__ float sh[8];
  v = warp_sum(v);
  if ((threadIdx.x & 31) == 0) sh[threadIdx.x >> 5] = v;
  __syncthreads();
  if (threadIdx.x == 0){
    float t = sh[0]+sh[1]+sh[2]+sh[3]+sh[4]+sh[5]+sh[6]+sh[7];
    atomicAdd(dst, (double)t);
  }
  __syncthreads();
}
__device__ __forceinline__ void block_maxf(int* dst, float v){
  __shared__ float sh[8];
  #pragma unroll
  for (int o=16; o; o>>=1) v = fmaxf(v, __shfl_down_sync(0xffffffffu, v, o));
  if ((threadIdx.x & 31) == 0) sh[threadIdx.x >> 5] = v;
  __syncthreads();
  if (threadIdx.x == 0){
    float m = sh[0];
    #pragma unroll
    for (int k=1;k<8;k++) m = fmaxf(m, sh[k]);
    atomicMax(dst, __float_as_int(m));
  }
  __syncthreads();
}
__device__ __forceinline__ void block_minf(int* dst, float v){
  __shared__ float sh[8];
  #pragma unroll
  for (int o=16; o; o>>=1) v = fminf(v, __shfl_down_sync(0xffffffffu, v, o));
  if ((threadIdx.x & 31) == 0) sh[threadIdx.x >> 5] = v;
  __syncthreads();
  if (threadIdx.x == 0){
    float m = sh[0];
    #pragma unroll
    for (int k=1;k<8;k++) m = fminf(m, sh[k]);
    atomicMin(dst, __float_as_int(m));
  }
  __syncthreads();
}

// ---------------- bodies ----------------
// soft_erode (7-pt cross), 4w x 4h x 2d tile; w-halos via shfl.
// NOTE: flag early-exit is warp-uniform (vb identical across the block).
__device__ __forceinline__ void erode_body(const float* __restrict__ src,
                                           float* __restrict__ dst, int tt, int et){
  int vb = tt >> 15;
  int f  = vb >> 1;
  if (g_nzS[f][et] == 0) return;
  int w0 = (tt & 31) << 2;
  int h0 = ((tt >> 5) & 31) << 2;
  int d0 = ((tt >> 10) & 31) << 1;
  const float* vbase = src + (long)vb*VOLSZ;
  const float INF = 1e30f;

  float4 C[4][4];
  #pragma unroll
  for (int pz=0; pz<4; ++pz){
    int dd = d0 - 1 + pz;
    bool zok = (unsigned)dd < DD;
    const float* pp = vbase + (zok ? dd : (dd < 0 ? 0 : DD-1))*HWS + h0*WW + w0;
    #pragma unroll
    for (int j=0;j<4;j++)
      C[pz][j] = selpad(ld4(pp + j*WW), zok, INF);
  }
  float4 HB[2][2];
  bool okm = (h0 > 0), okp = (h0 + 4 < HH);
  #pragma unroll
  for (int s=0;s<2;s++){
    const float* pp = vbase + (d0+s)*HWS;
    HB[s][0] = selpad(ld4(pp + (okm ? h0-1 : 0)*WW + w0), okm, INF);
    HB[s][1] = selpad(ld4(pp + (okp ? h0+4 : HH-1)*WW + w0), okp, INF);
  }
  float* obase = dst + (long)vb*VOLSZ + d0*HWS + h0*WW + w0;
  float anymax = 0.f;
  #pragma unroll
  for (int s=0;s<2;s++){
    #pragma unroll
    for (int j=0;j<4;j++){
      float4 v = C[s+1][j];
      float l = shleft(v.w, INF);
      float r = shright(v.x, INF);
      float4 w3;
      w3.x = fminf(fminf(l,   v.x), v.y);
      w3.y = fminf(fminf(v.x, v.y), v.z);
      w3.z = fminf(fminf(v.y, v.z), v.w);
      w3.w = fminf(fminf(v.z, v.w), r);
      float4 up = (j==0) ? HB[s][0] : C[s+1][j-1];
      float4 dn = (j==3) ? HB[s][1] : C[s+1][j+1];
      float4 m = f4min(w3, f4min(up, dn));
      m = f4min(m, f4min(C[s][j], C[s+2][j]));
      anymax = fmaxf(anymax, h4max(m));
      st4(obase + s*HWS + j*WW, m);
    }
  }
  if (anymax > 0.f) g_nzS[f][et+1] = 1;   // benign race
}

// dilate27(er) + skel update, 4w x 4h x 2d tile (single-pass, shfl halos)
__device__ __forceinline__ void dilate2_body(const float* __restrict__ img,
                                             const float* __restrict__ er,
                                             float* __restrict__ skel,
                                             int init, int tt, int dt){
  int vb = tt >> 15;
  int f  = vb >> 1;
  if (g_nzS[f][dt] == 0) return;
  int w0 = (tt & 31) << 2;
  int h0 = ((tt >> 5) & 31) << 2;
  int d0 = ((tt >> 10) & 31) << 1;
  const float* ebase = er + (long)vb*VOLSZ;
  const float4 N4 = make_float4(-1e30f,-1e30f,-1e30f,-1e30f);
  float4 out[2][4];
  #pragma unroll
  for (int j=0;j<4;j++){ out[0][j]=N4; out[1][j]=N4; }
  bool er_nz = (g_nzS[f][dt+1] != 0);
  if (er_nz){
    #pragma unroll
    for (int pz=0; pz<4; ++pz){
      int dd = d0 - 1 + pz;
      bool zok = (unsigned)dd < DD;
      const float* pp = ebase + (zok ? dd : (dd < 0 ? 0 : DD-1))*HWS;
      float4 rw[6];
      #pragma unroll
      for (int jr=0; jr<6; ++jr){
        int hh = h0 - 1 + jr;
        bool ok = zok & ((unsigned)hh < HH);
        const float* rp = pp + (((unsigned)hh < HH) ? hh : (hh < 0 ? 0 : HH-1))*WW + w0;
        rw[jr] = rw3s<true>(rp, ok);
      }
      float4 mh[4];
      #pragma unroll
      for (int j=0;j<4;j++) mh[j] = f4max(rw[j], f4max(rw[j+1], rw[j+2]));
      if (pz <= 2){
        #pragma unroll
        for (int j=0;j<4;j++) out[0][j] = f4max(out[0][j], mh[j]);
      }
      if (pz >= 1){
        #pragma unroll
        for (int j=0;j<4;j++) out[1][j] = f4max(out[1][j], mh[j]);
      }
    }
  } else {
    #pragma unroll
    for (int j=0;j<4;j++){
      out[0][j] = make_float4(0.f,0.f,0.f,0.f);
      out[1][j] = make_float4(0.f,0.f,0.f,0.f);
    }
  }
  long off = (long)vb*VOLSZ + d0*HWS + h0*WW + w0;
  #pragma unroll
  for (int s=0;s<2;s++){
    #pragma unroll
    for (int j=0;j<4;j++){
      float4 im = ld4(img + off + s*HWS + j*WW);
      float4 o = out[s][j];
      float4 dl = make_float4(fmaxf(im.x-o.x,0.f), fmaxf(im.y-o.y,0.f),
                              fmaxf(im.z-o.z,0.f), fmaxf(im.w-o.w,0.f));
      if (init){
        st4(skel + off + s*HWS + j*WW, dl);
      } else {
        float4 sv = ld4(skel + off + s*HWS + j*WW);
        sv.x += fmaxf(dl.x - sv.x*dl.x, 0.f);
        sv.y += fmaxf(dl.y - sv.y*dl.y, 0.f);
        sv.z += fmaxf(dl.z - sv.z*dl.z, 0.f);
        sv.w += fmaxf(dl.w - sv.w*dl.w, 0.f);
        st4(skel + off + s*HWS + j*WW, sv);
      }
    }
  }
}

// edt step k: acc += cur ; nxt = minpool27(cur). 2 fields (4 vols).
__device__ __forceinline__ void minpool_body(const float* __restrict__ cur,
                                             float* __restrict__ nxt,
                                             float* __restrict__ acc,
                                             int first, int tt, int k){
  if (g_nzM[k] == 0) return;
  int w0 = (tt & 31) << 2;
  int h0 = ((tt >> 5) & 31) << 2;
  int d  = (tt >> 10) & 63;
  int vb = tt >> 16;
  int sv = first ? ((vb < 2) ? vb : vb + 2) : vb;   // {Y0,Y1,Hd0,Hd1} in SRC
  const float* sb = cur + (long)sv*VOLSZ;
  long ob = (long)vb*VOLSZ + d*HWS + h0*WW + w0;
  float4 o[4];
  box27_4s<false>(sb, d, h0, w0, o);
  const float* p = sb + d*HWS + h0*WW + w0;
  float anymax = 0.f;
  #pragma unroll
  for (int j=0;j<4;j++){ anymax = fmaxf(anymax, h4max(o[j])); st4(nxt + ob + j*WW, o[j]); }
  if (first){
    #pragma unroll
    for (int j=0;j<4;j++) st4(acc + ob + j*WW, ld4(p + j*WW));
  } else {
    #pragma unroll
    for (int j=0;j<4;j++){
      float4 a = ld4(acc + ob + j*WW);
      float4 c = ld4(p + j*WW);
      a.x += c.x; a.y += c.y; a.z += c.z; a.w += c.w;
      st4(acc + ob + j*WW, a);
    }
  }
  if (anymax > 0.f) g_nzM[k+1] = 1;
}

// directional (Sobel) loss body — exact replica of reference kernel layout.
// w-halos via shfl (warp spans the 128-row; dz/dy skips are warp-uniform).
__device__ __forceinline__ void dir_body(const float* __restrict__ net,
                                         const int* __restrict__ tgt, int t){
  int i = t << 2;
  int b = i >> 20;
  int r = i & (VOLSZ-1);
  int d = r >> 14, hh = (r >> 7) & 127;
  const float* pb = net + i + b*VOLSZ;
  const int*   tb = tgt + i;
  float pgx[4]={0,0,0,0}, pgy[4]={0,0,0,0}, pgz[4]={0,0,0,0};
  float tgx[4]={0,0,0,0}, tgy[4]={0,0,0,0}, tgz[4]={0,0,0,0};
  #pragma unroll
  for (int dz=-1; dz<=1; ++dz){
    if ((unsigned)(d+dz) >= DD) continue;
    float cy = (dz==0) ? 2.f : 1.f;
    float cz = (float)dz;
    #pragma unroll
    for (int dy=-1; dy<=1; ++dy){
      if ((unsigned)(hh+dy) >= HH) continue;
      float cx = (dy==0) ? 2.f : 1.f;
      int off = dz*HWS + dy*WW;
      {
        const float* rp = pb + off;
        float vv[6];
        float4 v = ld4(rp);
        vv[1]=v.x; vv[2]=v.y; vv[3]=v.z; vv[4]=v.w;
        vv[0] = shleft(v.w, 0.f);
        vv[5] = shright(v.x, 0.f);
        #pragma unroll
        for (int k=0;k<4;k++){
          float dv = vv[k+2] - vv[k];
          float sv = vv[k] + 2.f*vv[k+1] + vv[k+2];
          pgx[k] += cx*dv; pgy[k] += cy*dv; pgz[k] += cz*sv;
        }
      }
      {
        const int* rp = tb + off;
        float vv[6];
        int4 v = *reinterpret_cast<const int4*>(rp);
        vv[1]=(float)v.x; vv[2]=(float)v.y; vv[3]=(float)v.z; vv[4]=(float)v.w;
        vv[0] = shleft(vv[4], 0.f);
        vv[5] = shright(vv[1], 0.f);
        #pragma unroll
        for (int k=0;k<4;k++){
          float dv = vv[k+2] - vv[k];
          float sv = vv[k] + 2.f*vv[k+1] + vv[k+2];
          tgx[k] += cx*dv; tgy[k] += cy*dv; tgz[k] += cz*sv;
        }
      }
    }
  }
  float acc = 0.f;
  #pragma unroll
  for (int k=0;k<4;k++){
    float np = sqrtf(pgx[k]*pgx[k] + pgy[k]*pgy[k] + pgz[k]*pgz[k]);
    float nt = sqrtf(tgx[k]*tgx[k] + tgy[k]*tgy[k] + tgz[k]*tgz[k]);
    float ip = 1.f / fmaxf(np, 1e-12f);
    float it = 1.f / fmaxf(nt, 1e-12f);
    float num = (pgx[k]*tgx[k] + pgy[k]*tgy[k] + pgz[k]*tgz[k]) * ip * it;
    float den = fmaxf((np*ip) * (nt*it), 1e-8f);
    acc += num / den;
  }
  block_add(&g_sums[S_DIR], acc);
}

// prob/y/hard + dice/CE/conn sums
__device__ __forceinline__ void init_body(const float* __restrict__ net,
                                          const int* __restrict__ tgt, int t){
  int i = t << 2;
  int b = i >> 20;
  float4 n0 = ld4(net + i + b*VOLSZ);
  float4 n1 = ld4(net + i + (b+1)*VOLSZ);
  int4   tg = *reinterpret_cast<const int4*>(tgt + i);
  float a[4] = {n0.x, n0.y, n0.z, n0.w};
  float c[4] = {n1.x, n1.y, n1.z, n1.w};
  int   l[4] = {tg.x, tg.y, tg.z, tg.w};
  float pv[4], yv[4], hv[4];
  float tp=0.f, fp=0.f, fn=0.f, ce=0.f, cn=0.f;
  #pragma unroll
  for (int k=0;k<4;k++){
    float y = (l[k] > 0) ? 1.f : 0.f;
    float p = 1.f / (1.f + expf(a[k] - c[k]));
    pv[k]=p; yv[k]=y; hv[k] = (p > 0.5f) ? 1.f : 0.f;
    tp += p*y; fp += p*(1.f-y); fn += (1.f-p)*y;
    float m = fmaxf(a[k], c[k]);
    float lse = m + logf(expf(a[k]-m) + expf(c[k]-m));
    ce += lse - ((l[k] > 0) ? c[k] : a[k]);
    cn += fabsf(((a[k] > 0.5f) ? 1.f : 0.f) - y)
        + fabsf(((c[k] > 0.5f) ? 1.f : 0.f) - y);
  }
  st4(g_SRC + i,          make_float4(yv[0],yv[1],yv[2],yv[3]));
  st4(g_SRC + NTOT + i,   make_float4(pv[0],pv[1],pv[2],pv[3]));
  st4(g_SRC + 2*NTOT + i, make_float4(hv[0],hv[1],hv[2],hv[3]));
  block_add(&g_sums[S_TP], tp);
  block_add(&g_sums[S_FP], fp);
  block_add(&g_sums[S_FN], fn);
  block_add(&g_sums[S_CE], ce);
  block_add(&g_sums[S_CONN], cn);
}

// ---------------- kernels ----------------
__global__ void zero_kernel(){
  int t = threadIdx.x;
  if (t < 14) g_sums[t] = 0.0;
  if (t < 2){
    g_maxT[t] = 0; g_maxP[t] = 0;
    g_minT[t] = 0x7f800000; g_minP[t] = 0x7f800000;
  }
  if (t < 17) g_nzM[t] = (t == 0) ? 1 : 0;
  if (t < 48){
    int f = t >> 4, s = t & 15;
    g_nzS[f][s] = (s == 0) ? 1 : 0;
  }
}

// fused [init | dir]
__global__ void __launch_bounds__(256) init_dir_kernel(const float* __restrict__ net,
                                                       const int* __restrict__ tgt){
  int bx = blockIdx.x, tid = threadIdx.x;
  if (bx < G_INIT) init_body(net, tgt, bx*256 + tid);
  else             dir_body(net, tgt, (bx - G_INIT)*256 + tid);
}

// L0: [erode gen0->1 | minpool step0]
__global__ void __launch_bounds__(256) combo_er0_mp0(const float* __restrict__ esrc,
                                                     float* __restrict__ edst,
                                                     float* __restrict__ mnxt,
                                                     float* __restrict__ macc){
  int bx = blockIdx.x, tid = threadIdx.x;
  if (bx < EB) erode_body(esrc, edst, bx*256 + tid, 0);
  else         minpool_body(esrc, mnxt, macc, 1, (bx - EB)*256 + tid, 0);
}

// pipelined: [dilate(img=gen k-1, er=gen k) | erode(gen k -> gen k+1) | minpool k]
__global__ void __launch_bounds__(256) combo_de_mp(const float* __restrict__ img,
                                                   const float* __restrict__ er,
                                                   float* __restrict__ skel,
                                                   int dinit, int dt,
                                                   float* __restrict__ edst, int et,
                                                   const float* __restrict__ mcur,
                                                   float* __restrict__ mnxt,
                                                   float* __restrict__ macc, int mk){
  int bx = blockIdx.x, tid = threadIdx.x;
  if (bx < DB)          dilate2_body(img, er, skel, dinit, bx*256 + tid, dt);
  else if (bx < DB+EB)  erode_body(er, edst, (bx - DB)*256 + tid, et);
  else                  minpool_body(mcur, mnxt, macc, 0, (bx - DB - EB)*256 + tid, mk);
}

// final dilate: [dilate | minpool]
__global__ void __launch_bounds__(256) combo_di_mp(const float* __restrict__ img,
                                                   const float* __restrict__ er,
                                                   float* __restrict__ skel,
                                                   int dinit, int dt,
                                                   const float* __restrict__ mcur,
                                                   float* __restrict__ mnxt,
                                                   float* __restrict__ macc, int mk){
  int bx = blockIdx.x, tid = threadIdx.x;
  if (bx < DB) dilate2_body(img, er, skel, dinit, bx*256 + tid, dt);
  else         minpool_body(mcur, mnxt, macc, 0, (bx - DB)*256 + tid, mk);
}

// tail minpool steps (normally early-exit)
__global__ void __launch_bounds__(256) mp_only(const float* __restrict__ mcur,
                                               float* __restrict__ mnxt,
                                               float* __restrict__ macc, int mk){
  minpool_body(mcur, mnxt, macc, 0, blockIdx.x*256 + threadIdx.x, mk);
}

// per-batch max/min of skel_radius (vectorized x4)
__global__ void __launch_bounds__(256) r1_kernel(){
  int t = blockIdx.x*256 + threadIdx.x;
  int i = t << 2;
  int b = i >> 20;
  float4 y   = ld4(g_SRC + i);
  float4 p   = ld4(g_SRC + NTOT + i);
  float4 hd  = ld4(g_SRC + 2*NTOT + i);
  float4 st  = ld4(g_SK + i);
  float4 sph = ld4(g_SK + 2*NTOT + i);
  float4 aT  = ld4(g_ACC + i);
  float4 aP  = ld4(g_ACC + NTOT + i);
  float mxT, mnT, mxP, mnP;
  {
    float s0 = aT.x*y.x*st.x, s1 = aT.y*y.y*st.y, s2 = aT.z*y.z*st.z, s3 = aT.w*y.w*st.w;
    mxT = fmaxf(fmaxf(s0,s1), fmaxf(s2,s3));
    mnT = fminf(fminf(s0,s1), fminf(s2,s3));
    float b0 = (sph.x*p.x > 0.5f) ? 1.f : 0.f;
    float b1 = (sph.y*p.y > 0.5f) ? 1.f : 0.f;
    float b2 = (sph.z*p.z > 0.5f) ? 1.f : 0.f;
    float b3 = (sph.w*p.w > 0.5f) ? 1.f : 0.f;
    float q0 = aP.x*hd.x*b0, q1 = aP.y*hd.y*b1, q2 = aP.z*hd.z*b2, q3 = aP.w*hd.w*b3;
    mxP = fmaxf(fmaxf(q0,q1), fmaxf(q2,q3));
    mnP = fminf(fminf(q0,q1), fminf(q2,q3));
  }
  block_maxf(&g_maxT[b], mxT);
  block_minf(&g_minT[b], mnT);
  block_maxf(&g_maxP[b], mxP);
  block_minf(&g_minP[b], mnP);
}

// all union-loss + clDice sums (vectorized x4)
__global__ void __launch_bounds__(256) r2_kernel(){
  int t = blockIdx.x*256 + threadIdx.x;
  int i = t << 2;
  int b = i >> 20;
  float4 y4   = ld4(g_SRC + i);
  float4 p4   = ld4(g_SRC + NTOT + i);
  float4 hd4  = ld4(g_SRC + 2*NTOT + i);
  float4 st4v = ld4(g_SK + i);
  float4 sp4  = ld4(g_SK + NTOT + i);
  float4 sph4 = ld4(g_SK + 2*NTOT + i);
  float4 aT4  = ld4(g_ACC + i);
  float4 aP4  = ld4(g_ACC + NTOT + i);
  float rmaxT = fmaxf(__int_as_float(g_maxT[b]), 1.f);
  float rminT = fmaxf(__int_as_float(g_minT[b]), 1.f);
  float rmaxP = fmaxf(__int_as_float(g_maxP[b]), 1.f);
  float rminP = fmaxf(__int_as_float(g_minP[b]), 1.f);
  float irT = 1.f/rmaxT, irP = 1.f/rmaxP;

  float I1=0.f, U1=0.f, I2=0.f, U2=0.f, C1=0.f, C2=0.f, C3=0.f, C4=0.f;
  float yv[4]={y4.x,y4.y,y4.z,y4.w}, pv[4]={p4.x,p4.y,p4.z,p4.w};
  float hv[4]={hd4.x,hd4.y,hd4.z,hd4.w}, sv[4]={st4v.x,st4v.y,st4v.z,st4v.w};
  float spv[4]={sp4.x,sp4.y,sp4.z,sp4.w}, shv[4]={sph4.x,sph4.y,sph4.z,sph4.w};
  float atv[4]={aT4.x,aT4.y,aT4.z,aT4.w}, apv[4]={aP4.x,aP4.y,aP4.z,aP4.w};
  #pragma unroll
  for (int k=0;k<4;k++){
    float y=yv[k], p=pv[k], hd=hv[k], st=sv[k], sp=spv[k], sph=shv[k];
    float dT  = atv[k] * y;
    float srT = dT * st;
    float q_vl = fminf(dT, rmaxT) * irT * y;
    float t1 = (rmaxT - srT + rminT) * irT;
    float q_sl = t1*t1 * st * st;
    float dP  = apv[k] * hd;
    float sb  = (sph * p > 0.5f) ? 1.f : 0.f;
    float srP = dP * sb;
    float q_vp = fminf(dP, rmaxP) * irP * p;
    float t2 = (rmaxP - srP + rminP) * irP;
    float q_sp = t2*t2 * sb * (sph * p);
    I1 += q_sp * powf(q_sp + 1e-4f, 0.7f) * q_vl;
    U1 += q_sp * (0.1f*q_sp + 0.9f*q_vl);
    I2 += q_sl * powf(q_vp + 1e-4f, 0.7f) * q_sl;
    U2 += q_sl * (0.1f*q_vp + 0.9f*q_sl);
    C1 += sp*y; C2 += sp; C3 += st*p; C4 += st;
  }
  block_add(&g_sums[S_I1], I1);
  block_add(&g_sums[S_U1], U1);
  block_add(&g_sums[S_I2], I2);
  block_add(&g_sums[S_U2], U2);
  block_add(&g_sums[S_CL1], C1);
  block_add(&g_sums[S_CL2], C2);
  block_add(&g_sums[S_CL3], C3);
  block_add(&g_sums[S_CL4], C4);
}

__global__ void final_kernel(float* __restrict__ out){
  double tp = g_sums[S_TP], fp = g_sums[S_FP], fn = g_sums[S_FN];
  double dice = -((2.0*tp + 1e-5) / (2.0*tp + fp + fn + 1e-5));
  double ce   = g_sums[S_CE] / (double)NTOT;
  double conn = g_sums[S_CONN] / (2.0 * (double)NTOT);
  double dir  = 1.0 - g_sums[S_DIR] / (double)NTOT;
  double tprec = (g_sums[S_CL1] + 1.0) / (g_sums[S_CL2] + 1.0);
  double tsens = (g_sums[S_CL3] + 1.0) / (g_sums[S_CL4] + 1.0);
  double cl = 1.0 - 2.0*tprec*tsens / (tprec + tsens);
  double u  = (1.0 - (g_sums[S_I1] + 1.0) / (g_sums[S_U1] + 1.0))
            + (1.0 - (g_sums[S_I2] + 1.0) / (g_sums[S_U2] + 1.0));
  out[0] = (float)(dice + ce + cl + dir + conn + u);
}

// ---------------- host orchestration ----------------
extern "C" void kernel_launch(void* const* d_in, const int* in_sizes, int n_in,
                              void* d_out, int out_size){
  (void)in_sizes; (void)n_in; (void)out_size;
  const float* net = (const float*)d_in[0];
  const int*   tgt = (const int*)d_in[1];
  float* out = (float*)d_out;

  float *SRC,*SK,*B0,*B1,*B2,*MA,*MBp,*ACC;
  cudaGetSymbolAddress((void**)&SRC, g_SRC);
  cudaGetSymbolAddress((void**)&SK,  g_SK);
  cudaGetSymbolAddress((void**)&B0,  g_B0);
  cudaGetSymbolAddress((void**)&B1,  g_B1);
  cudaGetSymbolAddress((void**)&B2,  g_B2);
  cudaGetSymbolAddress((void**)&MA,  g_MA);
  cudaGetSymbolAddress((void**)&MBp, g_MB);
  cudaGetSymbolAddress((void**)&ACC, g_ACC);

  zero_kernel<<<1,64>>>();
  init_dir_kernel<<<G_INIT+DIRB,256>>>(net, tgt);

  // skel generation buffers: gen0 = SRC, gen g>=1 lives in sb[(g-1)%3]
  float* sb3[3] = {B0, B1, B2};
  auto gbuf = [&](int g)->float*{ return sb3[(g-1)%3]; };
  // EDT ping-pong: step0 writes MA; step k>=1 reads mbufs[(k+1)&1], writes mbufs[k&1]
  float* mbufs[2] = {MA, MBp};

  combo_er0_mp0<<<EB+MB,256>>>(SRC, gbuf(1), MA, ACC);

  for (int k=1; k<=10; ++k){
    const float* img = (k==1) ? SRC : gbuf(k-1);
    combo_de_mp<<<DB+EB+MB,256>>>(img, gbuf(k), SK, (k==1)?1:0, k-1,
                                  gbuf(k+1), k,
                                  mbufs[(k+1)&1], mbufs[k&1], ACC, k);
  }
  combo_di_mp<<<DB+MB,256>>>(gbuf(10), gbuf(11), SK, 0, 10,
                             mbufs[(11+1)&1], mbufs[11&1], ACC, 11);
  for (int k=12; k<16; ++k)
    mp_only<<<MB,256>>>(mbufs[(k+1)&1], mbufs[k&1], ACC, k);

  r1_kernel<<<GS4,256>>>();
  r2_kernel<<<GS4,256>>>();
  final_kernel<<<1,1>>>(out);
}